// round 15
// baseline (speedup 1.0000x reference)
#include <cuda_runtime.h>
#include <cuda_bf16.h>
#include <math.h>
#include <stdint.h>

// Problem constants
#define D    1024
#define F    513          // rfft bins
#define FP   528          // padded F (mult of 8); N2 = 1056
#define N2   (2*FP)       // 1056: [0..F) = re, [FP..FP+F) = im, pads zero
#define BB   2
#define TT   2048
#define M4   (BB*TT)      // 4096
#define CC   10
#define NCH  64
#define CL   (TT/NCH)     // 32

#define DDSZ   ((size_t)D*D)
#define TWNSZ  ((size_t)N2*D)
#define XNSZ   ((size_t)M4*D)
#define FPLANE ((size_t)M4*N2)

// ======================= static device scratch =======================
__device__ float g_WTc [3*DDSZ];          // Wq^T | Wk^T | Wv^T
__device__ float g_F3  [3*FPLANE];        // fq | fk | fv planes (fp32)
__device__ float g_Sre [(size_t)BB*NCH*CC*FP];
__device__ float g_Sim [(size_t)BB*NCH*CC*FP];
// bf16 hi/lo pairs
__device__ __nv_bfloat16 g_TWh[TWNSZ],   g_TWl[TWNSZ];     // twiddles (split at build)
__device__ __nv_bfloat16 g_WTh[3*DDSZ],  g_WTl[3*DDSZ];
__device__ __nv_bfloat16 g_Woh[DDSZ],    g_Wol[DDSZ];
__device__ __nv_bfloat16 g_Xh [XNSZ],    g_Xl [XNSZ];
__device__ __nv_bfloat16 g_WFh[3*TWNSZ], g_WFl[3*TWNSZ];   // fused DFT weights
__device__ __nv_bfloat16 g_Gth[TWNSZ],   g_Gtl[TWNSZ];     // Wo @ TW^T
__device__ __nv_bfloat16 g_Rh [FPLANE],  g_Rl [FPLANE];

// ======================= small kernels =======================
__global__ void build_tw() {
    int d = blockIdx.x * blockDim.x + threadIdx.x;
    int n = blockIdx.y;
    if (d >= D) return;
    int f = (n < FP) ? n : n - FP;
    float v = 0.f;
    if (f < F) {
        int idx = (f * d) & (D - 1);                 // exact argument reduction
        float s, c;
        sincosf((float)idx * 6.135923151542565e-3f, &s, &c);  // 2*pi/1024
        v = (n < FP) ? c : -s;
    }
    size_t o = (size_t)n * D + d;
    __nv_bfloat16 hv = __float2bfloat16(v);
    g_TWh[o] = hv;
    g_TWl[o] = __float2bfloat16(v - __bfloat162float(hv));
}

__global__ void transpose3(const float* __restrict__ A0, const float* __restrict__ A1,
                           const float* __restrict__ A2) {
    __shared__ float tile[32][33];
    const float* A = (blockIdx.z == 0) ? A0 : (blockIdx.z == 1) ? A1 : A2;
    float* AT = g_WTc + (size_t)blockIdx.z * DDSZ;
    int x  = blockIdx.x * 32 + threadIdx.x;
    int y0 = blockIdx.y * 32 + threadIdx.y;
    #pragma unroll
    for (int i = 0; i < 32; i += 8)
        tile[threadIdx.y + i][threadIdx.x] = A[(size_t)(y0 + i) * D + x];
    __syncthreads();
    int x2 = blockIdx.y * 32 + threadIdx.x;
    int y2 = blockIdx.x * 32 + threadIdx.y;
    #pragma unroll
    for (int i = 0; i < 32; i += 8)
        AT[(size_t)(y2 + i) * D + x2] = tile[threadIdx.x][threadIdx.y + i];
}

// one launch: split WTcat, Wo, x into bf16 hi/lo
__global__ void split_all(const float* __restrict__ Wo, const float* __restrict__ x) {
    size_t i = (size_t)blockIdx.x * blockDim.x + threadIdx.x;
    const float* src;
    __nv_bfloat16 *h, *l;
    size_t off;
    if (i < 3*DDSZ) {
        src = g_WTc; h = g_WTh; l = g_WTl; off = i;
    } else if (i < 4*DDSZ) {
        src = Wo;    h = g_Woh; l = g_Wol; off = i - 3*DDSZ;
    } else if (i < 4*DDSZ + XNSZ) {
        src = x;     h = g_Xh;  l = g_Xl;  off = i - 4*DDSZ;
    } else return;
    float v = src[off];
    __nv_bfloat16 hv = __float2bfloat16(v);
    h[off] = hv;
    l[off] = __float2bfloat16(v - __bfloat162float(hv));
}

// ======================= HMMA (mma.sync) split-bf16 GEMM =======================
// C[m,n] = sum_k A[m,k]*B[n,k], fp32 accumulate; C = Ah*Bh + Ah*Bl + Al*Bh.
// FOUR CTAs per SM: 128 threads (4 warps), block tile 64x128, warp tile 64x32,
// k-chunk 16, 3-stage cp.async ring, one __syncthreads per chunk, 48B rows.
// Small barrier domain (4 warps) + 4 independent CTAs hide each other's stalls.
#define ROWB        48                    // bytes per smem row (16 bf16 + 8 pad)
#define TILE_A      (64*ROWB)             // 3072
#define TILE_B      (128*ROWB)            // 6144
#define OFF_AL      TILE_A                // 3072
#define OFF_BH      (2*TILE_A)            // 6144
#define OFF_BL      (2*TILE_A + TILE_B)   // 12288
#define STAGE_BYTES (2*TILE_A + 2*TILE_B) // 18432
#define NSTAGE      3
#define HG_SMEM     (NSTAGE*STAGE_BYTES)  // 55296  (x4 CTAs = 221184 <= 228K)

__device__ __forceinline__ uint32_t smem_u32(const void* p) {
    uint32_t a;
    asm("{ .reg .u64 t; cvta.to.shared.u64 t, %1; cvt.u32.u64 %0, t; }" : "=r"(a) : "l"(p));
    return a;
}
__device__ __forceinline__ void cp16z(uint32_t dst, const void* src, uint32_t srcsz) {
    asm volatile("cp.async.cg.shared.global [%0], [%1], 16, %2;"
                 :: "r"(dst), "l"(src), "r"(srcsz) : "memory");
}
__device__ __forceinline__ void cp_commit() {
    asm volatile("cp.async.commit_group;" ::: "memory");
}
template <int N>
__device__ __forceinline__ void cp_wait() {
    asm volatile("cp.async.wait_group %0;" :: "n"(N) : "memory");
}
__device__ __forceinline__ void ldm4(uint32_t* r, uint32_t addr) {
    asm volatile("ldmatrix.sync.aligned.m8n8.x4.shared.b16 {%0,%1,%2,%3}, [%4];"
        : "=r"(r[0]), "=r"(r[1]), "=r"(r[2]), "=r"(r[3]) : "r"(addr));
}
__device__ __forceinline__ void mma16816(float* d, const uint32_t* a, const uint32_t* b) {
    asm volatile(
        "mma.sync.aligned.m16n8k16.row.col.f32.bf16.bf16.f32 "
        "{%0,%1,%2,%3}, {%4,%5,%6,%7}, {%8,%9}, {%0,%1,%2,%3};"
        : "+f"(d[0]), "+f"(d[1]), "+f"(d[2]), "+f"(d[3])
        : "r"(a[0]), "r"(a[1]), "r"(a[2]), "r"(a[3]), "r"(b[0]), "r"(b[1]));
}

template <int BF16OUT>
__device__ __forceinline__ void hgemm_core(
    const __nv_bfloat16* __restrict__ Ah, const __nv_bfloat16* __restrict__ Al,
    const __nv_bfloat16* __restrict__ Bh, const __nv_bfloat16* __restrict__ Bl,
    float* __restrict__ Cf, __nv_bfloat16* __restrict__ Ch, __nv_bfloat16* __restrict__ Cl,
    int M, int N, int K, int mBase, int nBase, char* smem) {
    const uint32_t sbase = smem_u32(smem);
    const int tid  = threadIdx.x;
    const int lane = tid & 31;
    const int wc   = tid >> 5;          // 0..3 : 32-col slab (all warps share A rows)

    // --- per-thread cp.async assignments: 6 x 16B segments per k16 chunk ---
    // segs: [0,128) Ah  [128,256) Al  [256,512) Bh  [512,768) Bl
    const __nv_bfloat16* sp[6];
    uint32_t dof[6];
    uint32_t vmask = 0;
    #pragma unroll
    for (int i = 0; i < 6; i++) {
        int idx = tid + i * 128;        // 0..767
        const __nv_bfloat16* base;
        int row, seg, rowsTot, rbase;
        uint32_t off;
        if (idx < 256) {                // A tiles: 64 rows x 2 segs each
            int t = idx >> 7;           // 0=Ah 1=Al
            int rem = idx & 127;
            row = rem >> 1; seg = rem & 1;
            base = t ? Al : Ah;
            rowsTot = M; rbase = mBase;
            off = (uint32_t)(t * OFF_AL + row * ROWB + seg * 16);
        } else {                        // B tiles: 128 rows x 2 segs each
            int rem2 = idx - 256;
            int t = rem2 >> 8;          // 0=Bh 1=Bl
            int rem = rem2 & 255;
            row = rem >> 1; seg = rem & 1;
            base = t ? Bl : Bh;
            rowsTot = N; rbase = nBase;
            off = (uint32_t)(OFF_BH + t * TILE_B + row * ROWB + seg * 16);
        }
        int gr = rbase + row;
        bool valid = gr < rowsTot;
        if (valid) vmask |= (1u << i);
        int cr = valid ? gr : (rowsTot - 1);
        sp[i]  = base + (size_t)cr * K + seg * 8;
        dof[i] = off;
    }

    float acc[4][4][4];
    #pragma unroll
    for (int mt = 0; mt < 4; mt++)
        #pragma unroll
        for (int nt = 0; nt < 4; nt++)
            #pragma unroll
            for (int j = 0; j < 4; j++) acc[mt][nt][j] = 0.f;

    const int nk = K >> 4;              // k16 chunks

    // prologue: chunks 0,1 -> stages 0,1
    #pragma unroll
    for (int i = 0; i < 6; i++) cp16z(sbase + dof[i], sp[i], ((vmask >> i) & 1) << 4);
    cp_commit();
    #pragma unroll
    for (int i = 0; i < 6; i++) cp16z(sbase + STAGE_BYTES + dof[i], sp[i] + 16, ((vmask >> i) & 1) << 4);
    cp_commit();

    // ldmatrix per-lane intra-tile offsets (A shared by all warps)
    const uint32_t aoff = sbase
                        + (uint32_t)((lane & 15) * ROWB + (lane >> 4) * 16);
    const uint32_t boff = sbase + (uint32_t)(OFF_BH + wc * 32 * ROWB)
                        + (uint32_t)((lane & 7) * ROWB + ((lane >> 3) & 1) * 16
                                     + (lane >> 4) * 8 * ROWB);

    for (int c = 0; c < nk; c++) {
        cp_wait<1>();                   // chunk c landed
        __syncthreads();                // 4 warps done with stage being refilled
        if (c + 2 < nk) {               // prefetch c+2 into stage (c+2)%3
            const uint32_t so = sbase + ((c + 2) % NSTAGE) * STAGE_BYTES;
            const int k2 = (c + 2) << 4;
            #pragma unroll
            for (int i = 0; i < 6; i++)
                cp16z(so + dof[i], sp[i] + k2, ((vmask >> i) & 1) << 4);
        }
        cp_commit();                    // always commit (group accounting)

        const uint32_t st = ((uint32_t)(c % NSTAGE)) * STAGE_BYTES;
        const uint32_t ab = aoff + st;
        const uint32_t bb = boff + st;
        uint32_t a[4][4], bh[2][4], bl[2][4];
        #pragma unroll
        for (int mt = 0; mt < 4; mt++)
            ldm4(a[mt], ab + (uint32_t)(mt * 16 * ROWB));
        #pragma unroll
        for (int q = 0; q < 2; q++)
            ldm4(bh[q], bb + (uint32_t)(q * 16 * ROWB));
        #pragma unroll
        for (int q = 0; q < 2; q++)
            ldm4(bl[q], bb + (uint32_t)(TILE_B + q * 16 * ROWB));
        #pragma unroll
        for (int mt = 0; mt < 4; mt++)
            #pragma unroll
            for (int nt = 0; nt < 4; nt++)
                mma16816(acc[mt][nt], a[mt], &bh[nt >> 1][(nt & 1) * 2]);
        #pragma unroll
        for (int mt = 0; mt < 4; mt++)
            #pragma unroll
            for (int nt = 0; nt < 4; nt++)
                mma16816(acc[mt][nt], a[mt], &bl[nt >> 1][(nt & 1) * 2]);
        #pragma unroll
        for (int mt = 0; mt < 4; mt++)
            ldm4(a[mt], ab + (uint32_t)(OFF_AL + mt * 16 * ROWB));
        #pragma unroll
        for (int mt = 0; mt < 4; mt++)
            #pragma unroll
            for (int nt = 0; nt < 4; nt++)
                mma16816(acc[mt][nt], a[mt], &bh[nt >> 1][(nt & 1) * 2]);
    }

    // epilogue (predicated for ragged M/N tails)
    const int row0 = mBase + (lane >> 2);
    const int col0 = nBase + wc * 32 + (lane & 3) * 2;
    #pragma unroll
    for (int mt = 0; mt < 4; mt++) {
        #pragma unroll
        for (int nt = 0; nt < 4; nt++) {
            int cc2 = col0 + nt * 8;
            if (cc2 >= N) continue;
            #pragma unroll
            for (int half = 0; half < 2; half++) {
                int r = row0 + mt * 16 + half * 8;
                if (r >= M) continue;
                size_t pos = (size_t)r * N + cc2;
                float v0 = acc[mt][nt][half * 2 + 0];
                float v1 = acc[mt][nt][half * 2 + 1];
                if (BF16OUT) {
                    __nv_bfloat16 h0 = __float2bfloat16(v0);
                    __nv_bfloat16 h1 = __float2bfloat16(v1);
                    __nv_bfloat162 hp, lp;
                    hp.x = h0; hp.y = h1;
                    lp.x = __float2bfloat16(v0 - __bfloat162float(h0));
                    lp.y = __float2bfloat16(v1 - __bfloat162float(h1));
                    *reinterpret_cast<__nv_bfloat162*>(Ch + pos) = hp;
                    *reinterpret_cast<__nv_bfloat162*>(Cl + pos) = lp;
                } else {
                    *reinterpret_cast<float2*>(Cf + pos) = make_float2(v0, v1);
                }
            }
        }
    }
}

// big GEMMs (fp32 out): z batches A/B/C by aZ/bZ/cZ elements
__global__ __launch_bounds__(128, 4)
void hgemm_main(const __nv_bfloat16* __restrict__ Ah, const __nv_bfloat16* __restrict__ Al,
                const __nv_bfloat16* __restrict__ Bh, const __nv_bfloat16* __restrict__ Bl,
                float* __restrict__ Cf, int M, int N, int K,
                size_t aZ, size_t bZ, size_t cZ) {
    extern __shared__ char smem[];
    const size_t zA = (size_t)blockIdx.z * aZ;
    const size_t zB = (size_t)blockIdx.z * bZ;
    hgemm_core<0>(Ah + zA, Al + zA, Bh + zB, Bl + zB,
                  Cf + (size_t)blockIdx.z * cZ, nullptr, nullptr,
                  M, N, K, blockIdx.y * 64, blockIdx.x * 128, smem);
}

// weight-prep GEMMs (bf16 h/l out), all four in one launch:
//   z<3 : WF_z[N2,D] = NT(TW[N2,D], WT_z[D,D])
//   z=3 : Gt[D,N2]   = NT(Wo[D,D],  TW[N2,D])
__global__ __launch_bounds__(128, 4)
void hgemm_prep() {
    extern __shared__ char smem[];
    const int z = blockIdx.z;
    const __nv_bfloat16 *Ah, *Al, *Bh, *Bl;
    __nv_bfloat16 *Ch, *Cl;
    int M, N;
    if (z < 3) {
        M = N2; N = D;
        Ah = g_TWh; Al = g_TWl;
        Bh = g_WTh + (size_t)z * DDSZ; Bl = g_WTl + (size_t)z * DDSZ;
        Ch = g_WFh + (size_t)z * TWNSZ; Cl = g_WFl + (size_t)z * TWNSZ;
    } else {
        M = D; N = N2;
        Ah = g_Woh; Al = g_Wol;
        Bh = g_TWh; Bl = g_TWl;
        Ch = g_Gth; Cl = g_Gtl;
    }
    const int mBase = blockIdx.y * 64;
    const int nBase = blockIdx.x * 128;
    if (mBase >= M || nBase >= N) return;
    hgemm_core<1>(Ah, Al, Bh, Bl, nullptr, Ch, Cl, M, N, D, mBase, nBase, smem);
}

// ======================= scan kernels =======================
#define pFQ (g_F3)
#define pFKg (g_F3 + FPLANE)
#define pFVg (g_F3 + 2*FPLANE)

__global__ __launch_bounds__(FP) void scan_partial(const int* __restrict__ perms) {
    __shared__ float skr[F], ski[F];
    const int b = blockIdx.y, ch = blockIdx.x;
    const int tid = threadIdx.x;
    const int f = tid;
    int   g[CC];
    float ar[CC], ai[CC];
    if (f < F) {
        #pragma unroll
        for (int c = 0; c < CC; c++) { g[c] = perms[c * F + f]; ar[c] = 0.f; ai[c] = 0.f; }
    }
    const int t0 = ch * CL;
    for (int t = t0; t < t0 + CL; t++) {
        const size_t row = (size_t)(b * TT + t) * N2;
        for (int i = tid; i < F; i += blockDim.x) {
            skr[i] = pFKg[row + i];
            ski[i] = pFKg[row + FP + i];
        }
        __syncthreads();
        if (f < F) {
            float vr = pFVg[row + f], vi = pFVg[row + FP + f];
            #pragma unroll
            for (int c = 0; c < CC; c++) {
                float kr = skr[g[c]], ki = ski[g[c]];
                ar[c] = fmaf(kr, vr, fmaf(-ki, vi, ar[c]));
                ai[c] = fmaf(kr, vi, fmaf( ki, vr, ai[c]));
            }
        }
        __syncthreads();
    }
    if (f < F) {
        size_t base = (size_t)(b * NCH + ch) * CC * FP + f;
        #pragma unroll
        for (int c = 0; c < CC; c++) {
            g_Sre[base + (size_t)c * FP] = ar[c];
            g_Sim[base + (size_t)c * FP] = ai[c];
        }
    }
}

__global__ void scan_offsets() {
    int idx = blockIdx.x * blockDim.x + threadIdx.x;
    if (idx >= BB * CC * FP) return;
    int f = idx % FP;
    int c = (idx / FP) % CC;
    int b = idx / (FP * CC);
    float rr = 0.f, ri = 0.f;
    for (int ch = 0; ch < NCH; ch++) {
        size_t off = ((size_t)(b * NCH + ch) * CC + c) * FP + f;
        float vr = g_Sre[off], vi = g_Sim[off];
        g_Sre[off] = rr; g_Sim[off] = ri;
        rr += vr; ri += vi;
    }
}

__global__ __launch_bounds__(FP) void scan_final(const int* __restrict__ perms) {
    __shared__ float skr[F], ski[F], sqr[F], sqi[F];
    const int b = blockIdx.y, ch = blockIdx.x;
    const int tid = threadIdx.x;
    const int f = tid;
    int   g[CC];
    float ar[CC], ai[CC];
    float s = 0.f;
    if (f < F) {
        size_t base = (size_t)(b * NCH + ch) * CC * FP + f;
        #pragma unroll
        for (int c = 0; c < CC; c++) {
            g[c]  = perms[c * F + f];
            ar[c] = g_Sre[base + (size_t)c * FP];
            ai[c] = g_Sim[base + (size_t)c * FP];
        }
        s = ((f == 0 || f == F - 1) ? 1.f : 2.f) / ((float)CC * (float)D);
    }
    const int t0 = ch * CL;
    for (int t = t0; t < t0 + CL; t++) {
        const size_t row = (size_t)(b * TT + t) * N2;
        for (int i = tid; i < F; i += blockDim.x) {
            skr[i] = pFKg[row + i];
            ski[i] = pFKg[row + FP + i];
            sqr[i] = pFQ[row + i];
            sqi[i] = pFQ[row + FP + i];
        }
        __syncthreads();
        if (f < F) {
            float vr = pFVg[row + f], vi = pFVg[row + FP + f];
            float rr = 0.f, ri = 0.f;
            #pragma unroll
            for (int c = 0; c < CC; c++) {
                float kr = skr[g[c]], ki = ski[g[c]];
                ar[c] = fmaf(kr, vr, fmaf(-ki, vi, ar[c]));
                ai[c] = fmaf(kr, vi, fmaf( ki, vr, ai[c]));
                float qr = sqr[g[c]], qi = sqi[g[c]];
                rr = fmaf(qr, ar[c], fmaf( qi, ai[c], rr));
                ri = fmaf(qr, ai[c], fmaf(-qi, ar[c], ri));
            }
            float vRe = rr * s, vIm = ri * s;
            __nv_bfloat16 hRe = __float2bfloat16(vRe);
            __nv_bfloat16 hIm = __float2bfloat16(vIm);
            g_Rh[row + f]      = hRe;
            g_Rl[row + f]      = __float2bfloat16(vRe - __bfloat162float(hRe));
            g_Rh[row + FP + f] = hIm;
            g_Rl[row + FP + f] = __float2bfloat16(vIm - __bfloat162float(hIm));
        } else {
            __nv_bfloat16 z = __float2bfloat16(0.f);
            g_Rh[row + f]      = z; g_Rl[row + f]      = z;
            g_Rh[row + FP + f] = z; g_Rl[row + FP + f] = z;
        }
        __syncthreads();
    }
}

// ======================= host launcher =======================
extern "C" void kernel_launch(void* const* d_in, const int* in_sizes, int n_in,
                              void* d_out, int out_size) {
    (void)in_sizes; (void)n_in; (void)out_size;
    const float* x     = (const float*)d_in[0];
    const float* Wq    = (const float*)d_in[1];
    const float* Wk    = (const float*)d_in[2];
    const float* Wv    = (const float*)d_in[3];
    const float* Wo    = (const float*)d_in[4];
    const int*   perms = (const int*)  d_in[5];
    float* out = (float*)d_out;

    cudaFuncSetAttribute(hgemm_main, cudaFuncAttributeMaxDynamicSharedMemorySize, HG_SMEM);
    cudaFuncSetAttribute(hgemm_prep, cudaFuncAttributeMaxDynamicSharedMemorySize, HG_SMEM);

    __nv_bfloat16 *pXh, *pXl, *pWFh, *pWFl, *pGth, *pGtl, *pRh, *pRl;
    float *pF3;
    cudaGetSymbolAddress((void**)&pXh,  g_Xh);  cudaGetSymbolAddress((void**)&pXl,  g_Xl);
    cudaGetSymbolAddress((void**)&pWFh, g_WFh); cudaGetSymbolAddress((void**)&pWFl, g_WFl);
    cudaGetSymbolAddress((void**)&pGth, g_Gth); cudaGetSymbolAddress((void**)&pGtl, g_Gtl);
    cudaGetSymbolAddress((void**)&pRh,  g_Rh);  cudaGetSymbolAddress((void**)&pRl,  g_Rl);
    cudaGetSymbolAddress((void**)&pF3,  g_F3);

    // 0: twiddles (bf16 split written directly)
    build_tw<<<dim3(D / 256, N2), 256>>>();
    // 1: all three weight transposes
    transpose3<<<dim3(32, 32, 3), dim3(32, 8)>>>(Wq, Wk, Wv);
    // 2: bf16 splits (WTcat, Wo, x)
    {
        size_t total = 4*DDSZ + XNSZ;
        split_all<<<(unsigned)((total + 255) / 256), 256>>>(Wo, x);
    }
    // 3: all four weight-prep GEMMs in one launch (WF q,k,v + Gt)
    //    z<3: M=1056 -> 17 y-tiles of 64, N=1024 -> 8 x-tiles
    //    z=3: M=1024 -> 16 y-tiles,       N=1056 -> 9 x-tiles
    hgemm_prep<<<dim3(9, 17, 4), 128, HG_SMEM>>>();
    // 4: merged QKV projections+rfft: F3_z = NT(x, WF_z)
    hgemm_main<<<dim3(9, 64, 3), 128, HG_SMEM>>>(pXh, pXl, pWFh, pWFl,
        pF3, M4, N2, D, 0, TWNSZ, FPLANE);
    // 5-7: causal cumulative bind/unbind (chunked scan over T)
    scan_partial<<<dim3(NCH, BB), FP>>>(perms);
    scan_offsets<<<(BB * CC * FP + 255) / 256, 256>>>();
    scan_final  <<<dim3(NCH, BB), FP>>>(perms);
    // 8: irfft + output projection: out = NT(R, Gt)
    hgemm_main<<<dim3(8, 64, 1), 128, HG_SMEM>>>(pRh, pRl, pGth, pGtl,
        out, M4, D, N2, 0, 0, 0);
}

// round 16
// speedup vs baseline: 1.1630x; 1.1630x over previous
#include <cuda_runtime.h>
#include <cuda_bf16.h>
#include <math.h>
#include <stdint.h>

// Problem constants
#define D    1024
#define F    513          // rfft bins
#define FP   528          // padded F (mult of 8); N2 = 1056 = 33*32
#define N2   (2*FP)       // 1056: [0..F) = re, [FP..FP+F) = im, pads zero
#define BB   2
#define TT   2048
#define M4   (BB*TT)      // 4096
#define CC   10
#define NCH  64
#define CL   (TT/NCH)     // 32

#define DDSZ   ((size_t)D*D)
#define TWNSZ  ((size_t)N2*D)
#define XNSZ   ((size_t)M4*D)
#define FPLANE ((size_t)M4*N2)

// ======================= static device scratch =======================
__device__ float g_WTc [3*DDSZ];          // Wq^T | Wk^T | Wv^T
__device__ float g_F3  [3*FPLANE];        // fq | fk | fv planes (fp32)
__device__ float g_Sre [(size_t)BB*NCH*CC*FP];
__device__ float g_Sim [(size_t)BB*NCH*CC*FP];
// bf16 hi/lo pairs
__device__ __nv_bfloat16 g_TWh[TWNSZ],   g_TWl[TWNSZ];     // twiddles (split at build)
__device__ __nv_bfloat16 g_WTh[3*DDSZ],  g_WTl[3*DDSZ];
__device__ __nv_bfloat16 g_Woh[DDSZ],    g_Wol[DDSZ];
__device__ __nv_bfloat16 g_Xh [XNSZ],    g_Xl [XNSZ];
__device__ __nv_bfloat16 g_WFh[3*TWNSZ], g_WFl[3*TWNSZ];   // fused DFT weights
__device__ __nv_bfloat16 g_Gth[TWNSZ],   g_Gtl[TWNSZ];     // Wo @ TW^T
__device__ __nv_bfloat16 g_Rh [FPLANE],  g_Rl [FPLANE];

// ======================= stream/event pool (load-time init) =======================
struct HxStreams {
    cudaStream_t s2, s3;
    cudaEvent_t evSplit, evPrepQ, evGt, evQ;
    HxStreams() {
        cudaStreamCreateWithFlags(&s2, cudaStreamNonBlocking);
        cudaStreamCreateWithFlags(&s3, cudaStreamNonBlocking);
        cudaEventCreateWithFlags(&evSplit, cudaEventDisableTiming);
        cudaEventCreateWithFlags(&evPrepQ, cudaEventDisableTiming);
        cudaEventCreateWithFlags(&evGt,    cudaEventDisableTiming);
        cudaEventCreateWithFlags(&evQ,     cudaEventDisableTiming);
    }
};
static HxStreams g_hx;

// ======================= small kernels =======================
__global__ void build_tw() {
    int d = blockIdx.x * blockDim.x + threadIdx.x;
    int n = blockIdx.y;
    if (d >= D) return;
    int f = (n < FP) ? n : n - FP;
    float v = 0.f;
    if (f < F) {
        int idx = (f * d) & (D - 1);                 // exact argument reduction
        float s, c;
        sincosf((float)idx * 6.135923151542565e-3f, &s, &c);  // 2*pi/1024
        v = (n < FP) ? c : -s;
    }
    size_t o = (size_t)n * D + d;
    __nv_bfloat16 hv = __float2bfloat16(v);
    g_TWh[o] = hv;
    g_TWl[o] = __float2bfloat16(v - __bfloat162float(hv));
}

__global__ void transpose3(const float* __restrict__ A0, const float* __restrict__ A1,
                           const float* __restrict__ A2) {
    __shared__ float tile[32][33];
    const float* A = (blockIdx.z == 0) ? A0 : (blockIdx.z == 1) ? A1 : A2;
    float* AT = g_WTc + (size_t)blockIdx.z * DDSZ;
    int x  = blockIdx.x * 32 + threadIdx.x;
    int y0 = blockIdx.y * 32 + threadIdx.y;
    #pragma unroll
    for (int i = 0; i < 32; i += 8)
        tile[threadIdx.y + i][threadIdx.x] = A[(size_t)(y0 + i) * D + x];
    __syncthreads();
    int x2 = blockIdx.y * 32 + threadIdx.x;
    int y2 = blockIdx.x * 32 + threadIdx.y;
    #pragma unroll
    for (int i = 0; i < 32; i += 8)
        AT[(size_t)(y2 + i) * D + x2] = tile[threadIdx.x][threadIdx.y + i];
}

// one launch: split WTcat, Wo, x into bf16 hi/lo
__global__ void split_all(const float* __restrict__ Wo, const float* __restrict__ x) {
    size_t i = (size_t)blockIdx.x * blockDim.x + threadIdx.x;
    const float* src;
    __nv_bfloat16 *h, *l;
    size_t off;
    if (i < 3*DDSZ) {
        src = g_WTc; h = g_WTh; l = g_WTl; off = i;
    } else if (i < 4*DDSZ) {
        src = Wo;    h = g_Woh; l = g_Wol; off = i - 3*DDSZ;
    } else if (i < 4*DDSZ + XNSZ) {
        src = x;     h = g_Xh;  l = g_Xl;  off = i - 4*DDSZ;
    } else return;
    float v = src[off];
    __nv_bfloat16 hv = __float2bfloat16(v);
    h[off] = hv;
    l[off] = __float2bfloat16(v - __bfloat162float(hv));
}

// ======================= HMMA (mma.sync) split-bf16 GEMM (R13 core) ==========
// C[m,n] = sum_k A[m,k]*B[n,k], fp32 accumulate; C = Ah*Bh + Ah*Bl + Al*Bh.
// Block tile 128x128, 8 warps (2x4), warp tile 64x32, k-chunk 32,
// 2-stage cp.async double buffer, ONE __syncthreads per k32 chunk,
// ldmatrix fragment loads with cross-pass reuse. Requires K % 32 == 0.
#define ROWB        80                    // bytes per smem tile row (32 bf16 + 16 pad)
#define TILE_BYTES  (128*ROWB)            // 10240
#define STAGE_BYTES (4*TILE_BYTES)        // 40960: Ah | Al | Bh | Bl
#define HG_SMEM     (2*STAGE_BYTES)       // 81920

__device__ __forceinline__ uint32_t smem_u32(const void* p) {
    uint32_t a;
    asm("{ .reg .u64 t; cvta.to.shared.u64 t, %1; cvt.u32.u64 %0, t; }" : "=r"(a) : "l"(p));
    return a;
}
__device__ __forceinline__ void cp16z(uint32_t dst, const void* src, uint32_t srcsz) {
    asm volatile("cp.async.cg.shared.global [%0], [%1], 16, %2;"
                 :: "r"(dst), "l"(src), "r"(srcsz) : "memory");
}
__device__ __forceinline__ void cp_commit() {
    asm volatile("cp.async.commit_group;" ::: "memory");
}
template <int N>
__device__ __forceinline__ void cp_wait() {
    asm volatile("cp.async.wait_group %0;" :: "n"(N) : "memory");
}
__device__ __forceinline__ void ldm4(uint32_t* r, uint32_t addr) {
    asm volatile("ldmatrix.sync.aligned.m8n8.x4.shared.b16 {%0,%1,%2,%3}, [%4];"
        : "=r"(r[0]), "=r"(r[1]), "=r"(r[2]), "=r"(r[3]) : "r"(addr));
}
__device__ __forceinline__ void mma16816(float* d, const uint32_t* a, const uint32_t* b) {
    asm volatile(
        "mma.sync.aligned.m16n8k16.row.col.f32.bf16.bf16.f32 "
        "{%0,%1,%2,%3}, {%4,%5,%6,%7}, {%8,%9}, {%0,%1,%2,%3};"
        : "+f"(d[0]), "+f"(d[1]), "+f"(d[2]), "+f"(d[3])
        : "r"(a[0]), "r"(a[1]), "r"(a[2]), "r"(a[3]), "r"(b[0]), "r"(b[1]));
}

template <int BF16OUT>
__device__ __forceinline__ void hgemm_core(
    const __nv_bfloat16* __restrict__ Ah, const __nv_bfloat16* __restrict__ Al,
    const __nv_bfloat16* __restrict__ Bh, const __nv_bfloat16* __restrict__ Bl,
    float* __restrict__ Cf, __nv_bfloat16* __restrict__ Ch, __nv_bfloat16* __restrict__ Cl,
    int M, int N, int K, int mBase, int nBase, char* smem) {
    const uint32_t sbase = smem_u32(smem);
    const int tid  = threadIdx.x;
    const int lane = tid & 31;
    const int wid  = tid >> 5;
    const int wr   = wid >> 2;          // 0..1 : 64-row slab
    const int wc   = wid & 3;           // 0..3 : 32-col slab

    // --- per-thread cp.async assignments: 8 x 16B segments per k32 chunk ---
    const __nv_bfloat16* sp[8];
    uint32_t dof[8];
    uint32_t vmask = 0;
    #pragma unroll
    for (int i = 0; i < 8; i++) {
        int idx  = tid + i * 256;       // 0..2047
        int tile = idx >> 9;            // 0=Ah 1=Al 2=Bh 3=Bl  (512 segs per tile)
        int rem  = idx & 511;
        int row  = rem >> 2;
        int seg  = rem & 3;
        const __nv_bfloat16* base = (tile == 0) ? Ah : (tile == 1) ? Al : (tile == 2) ? Bh : Bl;
        int rowsTot = (tile < 2) ? M : N;
        int gr = ((tile < 2) ? mBase : nBase) + row;
        bool valid = gr < rowsTot;
        if (valid) vmask |= (1u << i);
        int cr = valid ? gr : (rowsTot - 1);
        sp[i]  = base + (size_t)cr * K + seg * 8;
        dof[i] = (uint32_t)(tile * TILE_BYTES + row * ROWB + seg * 16);
    }

    float acc[4][4][4];
    #pragma unroll
    for (int mt = 0; mt < 4; mt++)
        #pragma unroll
        for (int nt = 0; nt < 4; nt++)
            #pragma unroll
            for (int j = 0; j < 4; j++) acc[mt][nt][j] = 0.f;

    const int nk = K >> 5;              // k32 chunks

    // prologue: chunk 0 -> stage 0
    #pragma unroll
    for (int i = 0; i < 8; i++) cp16z(sbase + dof[i], sp[i], ((vmask >> i) & 1) << 4);
    cp_commit();

    // ldmatrix per-lane intra-tile offsets
    const uint32_t aoff = sbase + (uint32_t)(wr * 64 * ROWB)
                        + (uint32_t)((lane & 15) * ROWB + (lane >> 4) * 16);
    const uint32_t boff = sbase + (uint32_t)(2 * TILE_BYTES + wc * 32 * ROWB)
                        + (uint32_t)((lane & 7) * ROWB + ((lane >> 3) & 1) * 16
                                     + (lane >> 4) * 8 * ROWB);

    for (int c = 0; c < nk; c++) {
        cp_wait<0>();                   // chunk c landed
        __syncthreads();                // all warps done with the other stage
        if (c + 1 < nk) {               // prefetch c+1 into the freed stage
            const uint32_t so = sbase + ((c + 1) & 1) * STAGE_BYTES;
            const int k1 = (c + 1) << 5;
            #pragma unroll
            for (int i = 0; i < 8; i++)
                cp16z(so + dof[i], sp[i] + k1, ((vmask >> i) & 1) << 4);
            cp_commit();
        }

        const uint32_t st = ((uint32_t)(c & 1)) * STAGE_BYTES;
        #pragma unroll
        for (int kk = 0; kk < 2; kk++) {           // two k16 halves of the chunk
            const uint32_t ko = (uint32_t)(kk * 32);   // 16 bf16 = 32 bytes
            const uint32_t ab = aoff + st + ko;
            const uint32_t bb = boff + st + ko;
            uint32_t a[4][4], bh[2][4], bl[2][4];
            #pragma unroll
            for (int mt = 0; mt < 4; mt++)
                ldm4(a[mt], ab + (uint32_t)(mt * 16 * ROWB));
            #pragma unroll
            for (int q = 0; q < 2; q++)
                ldm4(bh[q], bb + (uint32_t)(q * 16 * ROWB));
            #pragma unroll
            for (int q = 0; q < 2; q++)
                ldm4(bl[q], bb + (uint32_t)(TILE_BYTES + q * 16 * ROWB));
            #pragma unroll
            for (int mt = 0; mt < 4; mt++)
                #pragma unroll
                for (int nt = 0; nt < 4; nt++)
                    mma16816(acc[mt][nt], a[mt], &bh[nt >> 1][(nt & 1) * 2]);
            #pragma unroll
            for (int mt = 0; mt < 4; mt++)
                #pragma unroll
                for (int nt = 0; nt < 4; nt++)
                    mma16816(acc[mt][nt], a[mt], &bl[nt >> 1][(nt & 1) * 2]);
            #pragma unroll
            for (int mt = 0; mt < 4; mt++)
                ldm4(a[mt], ab + (uint32_t)(TILE_BYTES + mt * 16 * ROWB));
            #pragma unroll
            for (int mt = 0; mt < 4; mt++)
                #pragma unroll
                for (int nt = 0; nt < 4; nt++)
                    mma16816(acc[mt][nt], a[mt], &bh[nt >> 1][(nt & 1) * 2]);
        }
    }

    // epilogue (predicated for ragged M/N tails)
    const int row0 = mBase + wr * 64 + (lane >> 2);
    const int col0 = nBase + wc * 32 + (lane & 3) * 2;
    #pragma unroll
    for (int mt = 0; mt < 4; mt++) {
        #pragma unroll
        for (int nt = 0; nt < 4; nt++) {
            int cc2 = col0 + nt * 8;
            if (cc2 >= N) continue;
            #pragma unroll
            for (int half = 0; half < 2; half++) {
                int r = row0 + mt * 16 + half * 8;
                if (r >= M) continue;
                size_t pos = (size_t)r * N + cc2;
                float v0 = acc[mt][nt][half * 2 + 0];
                float v1 = acc[mt][nt][half * 2 + 1];
                if (BF16OUT) {
                    __nv_bfloat16 h0 = __float2bfloat16(v0);
                    __nv_bfloat16 h1 = __float2bfloat16(v1);
                    __nv_bfloat162 hp, lp;
                    hp.x = h0; hp.y = h1;
                    lp.x = __float2bfloat16(v0 - __bfloat162float(h0));
                    lp.y = __float2bfloat16(v1 - __bfloat162float(h1));
                    *reinterpret_cast<__nv_bfloat162*>(Ch + pos) = hp;
                    *reinterpret_cast<__nv_bfloat162*>(Cl + pos) = lp;
                } else {
                    *reinterpret_cast<float2*>(Cf + pos) = make_float2(v0, v1);
                }
            }
        }
    }
}

// big GEMMs (fp32 out): z batches A/B/C by aZ/bZ/cZ elements
__global__ __launch_bounds__(256, 2)
void hgemm_main(const __nv_bfloat16* __restrict__ Ah, const __nv_bfloat16* __restrict__ Al,
                const __nv_bfloat16* __restrict__ Bh, const __nv_bfloat16* __restrict__ Bl,
                float* __restrict__ Cf, int M, int N, int K,
                size_t aZ, size_t bZ, size_t cZ) {
    extern __shared__ char smem[];
    const size_t zA = (size_t)blockIdx.z * aZ;
    const size_t zB = (size_t)blockIdx.z * bZ;
    hgemm_core<0>(Ah + zA, Al + zA, Bh + zB, Bl + zB,
                  Cf + (size_t)blockIdx.z * cZ, nullptr, nullptr,
                  M, N, K, blockIdx.y * 128, blockIdx.x * 128, smem);
}

// weight-prep GEMMs (bf16 h/l out), zbase selects the slice:
//   z<3 : WF_z[N2,D] = NT(TW[N2,D], WT_z[D,D])
//   z=3 : Gt[D,N2]   = NT(Wo[D,D],  TW[N2,D])
__global__ __launch_bounds__(256, 2)
void hgemm_prep(int zbase) {
    extern __shared__ char smem[];
    const int z = blockIdx.z + zbase;
    const __nv_bfloat16 *Ah, *Al, *Bh, *Bl;
    __nv_bfloat16 *Ch, *Cl;
    int M, N;
    if (z < 3) {
        M = N2; N = D;
        Ah = g_TWh; Al = g_TWl;
        Bh = g_WTh + (size_t)z * DDSZ; Bl = g_WTl + (size_t)z * DDSZ;
        Ch = g_WFh + (size_t)z * TWNSZ; Cl = g_WFl + (size_t)z * TWNSZ;
    } else {
        M = D; N = N2;
        Ah = g_Woh; Al = g_Wol;
        Bh = g_TWh; Bl = g_TWl;
        Ch = g_Gth; Cl = g_Gtl;
    }
    const int mBase = blockIdx.y * 128;
    const int nBase = blockIdx.x * 128;
    if (mBase >= M || nBase >= N) return;
    hgemm_core<1>(Ah, Al, Bh, Bl, nullptr, Ch, Cl, M, N, D, mBase, nBase, smem);
}

// ======================= scan kernels =======================
#define pFQ (g_F3)
#define pFKg (g_F3 + FPLANE)
#define pFVg (g_F3 + 2*FPLANE)

__global__ __launch_bounds__(FP) void scan_partial(const int* __restrict__ perms) {
    __shared__ float skr[F], ski[F];
    const int b = blockIdx.y, ch = blockIdx.x;
    const int tid = threadIdx.x;
    const int f = tid;
    int   g[CC];
    float ar[CC], ai[CC];
    if (f < F) {
        #pragma unroll
        for (int c = 0; c < CC; c++) { g[c] = perms[c * F + f]; ar[c] = 0.f; ai[c] = 0.f; }
    }
    const int t0 = ch * CL;
    for (int t = t0; t < t0 + CL; t++) {
        const size_t row = (size_t)(b * TT + t) * N2;
        for (int i = tid; i < F; i += blockDim.x) {
            skr[i] = pFKg[row + i];
            ski[i] = pFKg[row + FP + i];
        }
        __syncthreads();
        if (f < F) {
            float vr = pFVg[row + f], vi = pFVg[row + FP + f];
            #pragma unroll
            for (int c = 0; c < CC; c++) {
                float kr = skr[g[c]], ki = ski[g[c]];
                ar[c] = fmaf(kr, vr, fmaf(-ki, vi, ar[c]));
                ai[c] = fmaf(kr, vi, fmaf( ki, vr, ai[c]));
            }
        }
        __syncthreads();
    }
    if (f < F) {
        size_t base = (size_t)(b * NCH + ch) * CC * FP + f;
        #pragma unroll
        for (int c = 0; c < CC; c++) {
            g_Sre[base + (size_t)c * FP] = ar[c];
            g_Sim[base + (size_t)c * FP] = ai[c];
        }
    }
}

__global__ void scan_offsets() {
    int idx = blockIdx.x * blockDim.x + threadIdx.x;
    if (idx >= BB * CC * FP) return;
    int f = idx % FP;
    int c = (idx / FP) % CC;
    int b = idx / (FP * CC);
    float rr = 0.f, ri = 0.f;
    for (int ch = 0; ch < NCH; ch++) {
        size_t off = ((size_t)(b * NCH + ch) * CC + c) * FP + f;
        float vr = g_Sre[off], vi = g_Sim[off];
        g_Sre[off] = rr; g_Sim[off] = ri;
        rr += vr; ri += vi;
    }
}

__global__ __launch_bounds__(FP) void scan_final(const int* __restrict__ perms) {
    __shared__ float skr[F], ski[F], sqr[F], sqi[F];
    const int b = blockIdx.y, ch = blockIdx.x;
    const int tid = threadIdx.x;
    const int f = tid;
    int   g[CC];
    float ar[CC], ai[CC];
    float s = 0.f;
    if (f < F) {
        size_t base = (size_t)(b * NCH + ch) * CC * FP + f;
        #pragma unroll
        for (int c = 0; c < CC; c++) {
            g[c]  = perms[c * F + f];
            ar[c] = g_Sre[base + (size_t)c * FP];
            ai[c] = g_Sim[base + (size_t)c * FP];
        }
        s = ((f == 0 || f == F - 1) ? 1.f : 2.f) / ((float)CC * (float)D);
    }
    const int t0 = ch * CL;
    for (int t = t0; t < t0 + CL; t++) {
        const size_t row = (size_t)(b * TT + t) * N2;
        for (int i = tid; i < F; i += blockDim.x) {
            skr[i] = pFKg[row + i];
            ski[i] = pFKg[row + FP + i];
            sqr[i] = pFQ[row + i];
            sqi[i] = pFQ[row + FP + i];
        }
        __syncthreads();
        if (f < F) {
            float vr = pFVg[row + f], vi = pFVg[row + FP + f];
            float rr = 0.f, ri = 0.f;
            #pragma unroll
            for (int c = 0; c < CC; c++) {
                float kr = skr[g[c]], ki = ski[g[c]];
                ar[c] = fmaf(kr, vr, fmaf(-ki, vi, ar[c]));
                ai[c] = fmaf(kr, vi, fmaf( ki, vr, ai[c]));
                float qr = sqr[g[c]], qi = sqi[g[c]];
                rr = fmaf(qr, ar[c], fmaf( qi, ai[c], rr));
                ri = fmaf(qr, ai[c], fmaf(-qi, ar[c], ri));
            }
            float vRe = rr * s, vIm = ri * s;
            __nv_bfloat16 hRe = __float2bfloat16(vRe);
            __nv_bfloat16 hIm = __float2bfloat16(vIm);
            g_Rh[row + f]      = hRe;
            g_Rl[row + f]      = __float2bfloat16(vRe - __bfloat162float(hRe));
            g_Rh[row + FP + f] = hIm;
            g_Rl[row + FP + f] = __float2bfloat16(vIm - __bfloat162float(hIm));
        } else {
            __nv_bfloat16 z = __float2bfloat16(0.f);
            g_Rh[row + f]      = z; g_Rl[row + f]      = z;
            g_Rh[row + FP + f] = z; g_Rl[row + FP + f] = z;
        }
        __syncthreads();
    }
}

// ======================= host launcher =======================
extern "C" void kernel_launch(void* const* d_in, const int* in_sizes, int n_in,
                              void* d_out, int out_size) {
    (void)in_sizes; (void)n_in; (void)out_size;
    const float* x     = (const float*)d_in[0];
    const float* Wq    = (const float*)d_in[1];
    const float* Wk    = (const float*)d_in[2];
    const float* Wv    = (const float*)d_in[3];
    const float* Wo    = (const float*)d_in[4];
    const int*   perms = (const int*)  d_in[5];
    float* out = (float*)d_out;

    cudaFuncSetAttribute(hgemm_main, cudaFuncAttributeMaxDynamicSharedMemorySize, HG_SMEM);
    cudaFuncSetAttribute(hgemm_prep, cudaFuncAttributeMaxDynamicSharedMemorySize, HG_SMEM);

    __nv_bfloat16 *pXh, *pXl, *pWFh, *pWFl, *pGth, *pGtl, *pRh, *pRl;
    float *pF3;
    cudaGetSymbolAddress((void**)&pXh,  g_Xh);  cudaGetSymbolAddress((void**)&pXl,  g_Xl);
    cudaGetSymbolAddress((void**)&pWFh, g_WFh); cudaGetSymbolAddress((void**)&pWFl, g_WFl);
    cudaGetSymbolAddress((void**)&pGth, g_Gth); cudaGetSymbolAddress((void**)&pGtl, g_Gtl);
    cudaGetSymbolAddress((void**)&pRh,  g_Rh);  cudaGetSymbolAddress((void**)&pRl,  g_Rl);
    cudaGetSymbolAddress((void**)&pF3,  g_F3);

    // ---- main stream (capture stream): front-end prep ----
    build_tw<<<dim3(D / 256, N2), 256>>>();
    transpose3<<<dim3(32, 32, 3), dim3(32, 8)>>>(Wq, Wk, Wv);
    {
        size_t total = 4*DDSZ + XNSZ;
        split_all<<<(unsigned)((total + 255) / 256), 256>>>(Wo, x);
    }
    cudaEventRecord(g_hx.evSplit, 0);

    // ---- fork s2: Gt prep (z=3), needed only by the final out-GEMM ----
    cudaStreamWaitEvent(g_hx.s2, g_hx.evSplit, 0);
    hgemm_prep<<<dim3(9, 8, 1), 256, HG_SMEM, g_hx.s2>>>(3);
    cudaEventRecord(g_hx.evGt, g_hx.s2);

    // ---- main stream: WF prep for q,k,v ----
    hgemm_prep<<<dim3(8, 9, 3), 256, HG_SMEM>>>(0);
    cudaEventRecord(g_hx.evPrepQ, 0);

    // ---- fork s3: FQ projection (z=0) — not needed until scan_final ----
    cudaStreamWaitEvent(g_hx.s3, g_hx.evPrepQ, 0);
    hgemm_main<<<dim3(9, 32, 1), 256, HG_SMEM, g_hx.s3>>>(pXh, pXl, pWFh, pWFl,
        pF3, M4, N2, D, 0, 0, 0);
    cudaEventRecord(g_hx.evQ, g_hx.s3);

    // ---- main stream: FK/FV projections (z=1,2), then the kv-only scans ----
    hgemm_main<<<dim3(9, 32, 2), 256, HG_SMEM>>>(pXh, pXl,
        pWFh + TWNSZ, pWFl + TWNSZ, pF3 + FPLANE, M4, N2, D, 0, TWNSZ, FPLANE);
    scan_partial<<<dim3(NCH, BB), FP>>>(perms);
    scan_offsets<<<(BB * CC * FP + 255) / 256, 256>>>();

    // ---- join FQ, run final scan; join Gt, run output GEMM ----
    cudaStreamWaitEvent(0, g_hx.evQ, 0);
    scan_final<<<dim3(NCH, BB), FP>>>(perms);
    cudaStreamWaitEvent(0, g_hx.evGt, 0);
    hgemm_main<<<dim3(8, 32, 1), 256, HG_SMEM>>>(pRh, pRl, pGth, pGtl,
        out, M4, D, N2, 0, 0, 0);
}

// round 17
// speedup vs baseline: 1.1734x; 1.0090x over previous
#include <cuda_runtime.h>
#include <cuda_bf16.h>
#include <math.h>
#include <stdint.h>

// Problem constants
#define D    1024
#define F    513          // rfft bins
#define NF   513
#define IMB  512          // im bin f stored at column IMB+f, f in [1,512)
#define N2   1024         // packed freq planes: [0..513)=re, [513..1024)=im f=1..511
#define BB   2
#define TT   2048
#define M4   (BB*TT)      // 4096
#define CC   10
#define NCH  64
#define CL   (TT/NCH)     // 32

#define DDSZ   ((size_t)D*D)
#define TWNSZ  ((size_t)N2*D)     // = DDSZ
#define XNSZ   ((size_t)M4*D)
#define FPLANE ((size_t)M4*N2)

// ======================= static device scratch =======================
__device__ float g_WTc [3*DDSZ];          // Wq^T | Wk^T | Wv^T
__device__ float g_F3  [3*FPLANE];        // fq | fk | fv packed planes (fp32)
__device__ float g_Sre [(size_t)BB*NCH*CC*NF];
__device__ float g_Sim [(size_t)BB*NCH*CC*NF];
// bf16 hi/lo pairs
__device__ __nv_bfloat16 g_TWh[TWNSZ],   g_TWl[TWNSZ];     // packed DFT rows
__device__ __nv_bfloat16 g_WTh[3*DDSZ],  g_WTl[3*DDSZ];
__device__ __nv_bfloat16 g_Woh[DDSZ],    g_Wol[DDSZ];
__device__ __nv_bfloat16 g_Xh [XNSZ],    g_Xl [XNSZ];
__device__ __nv_bfloat16 g_WFh[3*TWNSZ], g_WFl[3*TWNSZ];   // fused DFT weights
__device__ __nv_bfloat16 g_Gth[TWNSZ],   g_Gtl[TWNSZ];     // Wo @ TW^T
__device__ __nv_bfloat16 g_Rh [FPLANE],  g_Rl [FPLANE];

// ======================= small kernels =======================
// packed DFT rows: n<513 -> cos(2*pi*n*d/D); n>=513 -> -sin(2*pi*(n-512)*d/D)
__global__ void build_tw() {
    int d = blockIdx.x * blockDim.x + threadIdx.x;
    int n = blockIdx.y;
    if (d >= D) return;
    int f = (n < NF) ? n : n - IMB;
    int idx = (f * d) & (D - 1);                 // exact argument reduction
    float s, c;
    sincosf((float)idx * 6.135923151542565e-3f, &s, &c);  // 2*pi/1024
    float v = (n < NF) ? c : -s;
    size_t o = (size_t)n * D + d;
    __nv_bfloat16 hv = __float2bfloat16(v);
    g_TWh[o] = hv;
    g_TWl[o] = __float2bfloat16(v - __bfloat162float(hv));
}

__global__ void transpose3(const float* __restrict__ A0, const float* __restrict__ A1,
                           const float* __restrict__ A2) {
    __shared__ float tile[32][33];
    const float* A = (blockIdx.z == 0) ? A0 : (blockIdx.z == 1) ? A1 : A2;
    float* AT = g_WTc + (size_t)blockIdx.z * DDSZ;
    int x  = blockIdx.x * 32 + threadIdx.x;
    int y0 = blockIdx.y * 32 + threadIdx.y;
    #pragma unroll
    for (int i = 0; i < 32; i += 8)
        tile[threadIdx.y + i][threadIdx.x] = A[(size_t)(y0 + i) * D + x];
    __syncthreads();
    int x2 = blockIdx.y * 32 + threadIdx.x;
    int y2 = blockIdx.x * 32 + threadIdx.y;
    #pragma unroll
    for (int i = 0; i < 32; i += 8)
        AT[(size_t)(y2 + i) * D + x2] = tile[threadIdx.x][threadIdx.y + i];
}

// one launch: split WTcat, Wo, x into bf16 hi/lo
__global__ void split_all(const float* __restrict__ Wo, const float* __restrict__ x) {
    size_t i = (size_t)blockIdx.x * blockDim.x + threadIdx.x;
    const float* src;
    __nv_bfloat16 *h, *l;
    size_t off;
    if (i < 3*DDSZ) {
        src = g_WTc; h = g_WTh; l = g_WTl; off = i;
    } else if (i < 4*DDSZ) {
        src = Wo;    h = g_Woh; l = g_Wol; off = i - 3*DDSZ;
    } else if (i < 4*DDSZ + XNSZ) {
        src = x;     h = g_Xh;  l = g_Xl;  off = i - 4*DDSZ;
    } else return;
    float v = src[off];
    __nv_bfloat16 hv = __float2bfloat16(v);
    h[off] = hv;
    l[off] = __float2bfloat16(v - __bfloat162float(hv));
}

// ======================= HMMA (mma.sync) split-bf16 GEMM (R13 core) ==========
// C[m,n] = sum_k A[m,k]*B[n,k], fp32 accumulate; C = Ah*Bh + Ah*Bl + Al*Bh.
// Block tile 128x128, 8 warps (2x4), warp tile 64x32, k-chunk 32,
// 2-stage cp.async double buffer, ONE __syncthreads per k32 chunk,
// ldmatrix fragment loads with cross-pass reuse. Requires K % 32 == 0.
#define ROWB        80                    // bytes per smem tile row (32 bf16 + 16 pad)
#define TILE_BYTES  (128*ROWB)            // 10240
#define STAGE_BYTES (4*TILE_BYTES)        // 40960: Ah | Al | Bh | Bl
#define HG_SMEM     (2*STAGE_BYTES)       // 81920

__device__ __forceinline__ uint32_t smem_u32(const void* p) {
    uint32_t a;
    asm("{ .reg .u64 t; cvta.to.shared.u64 t, %1; cvt.u32.u64 %0, t; }" : "=r"(a) : "l"(p));
    return a;
}
__device__ __forceinline__ void cp16z(uint32_t dst, const void* src, uint32_t srcsz) {
    asm volatile("cp.async.cg.shared.global [%0], [%1], 16, %2;"
                 :: "r"(dst), "l"(src), "r"(srcsz) : "memory");
}
__device__ __forceinline__ void cp_commit() {
    asm volatile("cp.async.commit_group;" ::: "memory");
}
template <int N>
__device__ __forceinline__ void cp_wait() {
    asm volatile("cp.async.wait_group %0;" :: "n"(N) : "memory");
}
__device__ __forceinline__ void ldm4(uint32_t* r, uint32_t addr) {
    asm volatile("ldmatrix.sync.aligned.m8n8.x4.shared.b16 {%0,%1,%2,%3}, [%4];"
        : "=r"(r[0]), "=r"(r[1]), "=r"(r[2]), "=r"(r[3]) : "r"(addr));
}
__device__ __forceinline__ void mma16816(float* d, const uint32_t* a, const uint32_t* b) {
    asm volatile(
        "mma.sync.aligned.m16n8k16.row.col.f32.bf16.bf16.f32 "
        "{%0,%1,%2,%3}, {%4,%5,%6,%7}, {%8,%9}, {%0,%1,%2,%3};"
        : "+f"(d[0]), "+f"(d[1]), "+f"(d[2]), "+f"(d[3])
        : "r"(a[0]), "r"(a[1]), "r"(a[2]), "r"(a[3]), "r"(b[0]), "r"(b[1]));
}

template <int BF16OUT>
__device__ __forceinline__ void hgemm_core(
    const __nv_bfloat16* __restrict__ Ah, const __nv_bfloat16* __restrict__ Al,
    const __nv_bfloat16* __restrict__ Bh, const __nv_bfloat16* __restrict__ Bl,
    float* __restrict__ Cf, __nv_bfloat16* __restrict__ Ch, __nv_bfloat16* __restrict__ Cl,
    int M, int N, int K, int mBase, int nBase, char* smem) {
    const uint32_t sbase = smem_u32(smem);
    const int tid  = threadIdx.x;
    const int lane = tid & 31;
    const int wid  = tid >> 5;
    const int wr   = wid >> 2;          // 0..1 : 64-row slab
    const int wc   = wid & 3;           // 0..3 : 32-col slab

    // --- per-thread cp.async assignments: 8 x 16B segments per k32 chunk ---
    const __nv_bfloat16* sp[8];
    uint32_t dof[8];
    uint32_t vmask = 0;
    #pragma unroll
    for (int i = 0; i < 8; i++) {
        int idx  = tid + i * 256;       // 0..2047
        int tile = idx >> 9;            // 0=Ah 1=Al 2=Bh 3=Bl  (512 segs per tile)
        int rem  = idx & 511;
        int row  = rem >> 2;
        int seg  = rem & 3;
        const __nv_bfloat16* base = (tile == 0) ? Ah : (tile == 1) ? Al : (tile == 2) ? Bh : Bl;
        int rowsTot = (tile < 2) ? M : N;
        int gr = ((tile < 2) ? mBase : nBase) + row;
        bool valid = gr < rowsTot;
        if (valid) vmask |= (1u << i);
        int cr = valid ? gr : (rowsTot - 1);
        sp[i]  = base + (size_t)cr * K + seg * 8;
        dof[i] = (uint32_t)(tile * TILE_BYTES + row * ROWB + seg * 16);
    }

    float acc[4][4][4];
    #pragma unroll
    for (int mt = 0; mt < 4; mt++)
        #pragma unroll
        for (int nt = 0; nt < 4; nt++)
            #pragma unroll
            for (int j = 0; j < 4; j++) acc[mt][nt][j] = 0.f;

    const int nk = K >> 5;              // k32 chunks

    // prologue: chunk 0 -> stage 0
    #pragma unroll
    for (int i = 0; i < 8; i++) cp16z(sbase + dof[i], sp[i], ((vmask >> i) & 1) << 4);
    cp_commit();

    // ldmatrix per-lane intra-tile offsets
    const uint32_t aoff = sbase + (uint32_t)(wr * 64 * ROWB)
                        + (uint32_t)((lane & 15) * ROWB + (lane >> 4) * 16);
    const uint32_t boff = sbase + (uint32_t)(2 * TILE_BYTES + wc * 32 * ROWB)
                        + (uint32_t)((lane & 7) * ROWB + ((lane >> 3) & 1) * 16
                                     + (lane >> 4) * 8 * ROWB);

    for (int c = 0; c < nk; c++) {
        cp_wait<0>();                   // chunk c landed
        __syncthreads();                // all warps done with the other stage
        if (c + 1 < nk) {               // prefetch c+1 into the freed stage
            const uint32_t so = sbase + ((c + 1) & 1) * STAGE_BYTES;
            const int k1 = (c + 1) << 5;
            #pragma unroll
            for (int i = 0; i < 8; i++)
                cp16z(so + dof[i], sp[i] + k1, ((vmask >> i) & 1) << 4);
            cp_commit();
        }

        const uint32_t st = ((uint32_t)(c & 1)) * STAGE_BYTES;
        #pragma unroll
        for (int kk = 0; kk < 2; kk++) {           // two k16 halves of the chunk
            const uint32_t ko = (uint32_t)(kk * 32);   // 16 bf16 = 32 bytes
            const uint32_t ab = aoff + st + ko;
            const uint32_t bb = boff + st + ko;
            uint32_t a[4][4], bh[2][4], bl[2][4];
            #pragma unroll
            for (int mt = 0; mt < 4; mt++)
                ldm4(a[mt], ab + (uint32_t)(mt * 16 * ROWB));
            #pragma unroll
            for (int q = 0; q < 2; q++)
                ldm4(bh[q], bb + (uint32_t)(q * 16 * ROWB));
            #pragma unroll
            for (int q = 0; q < 2; q++)
                ldm4(bl[q], bb + (uint32_t)(TILE_BYTES + q * 16 * ROWB));
            #pragma unroll
            for (int mt = 0; mt < 4; mt++)
                #pragma unroll
                for (int nt = 0; nt < 4; nt++)
                    mma16816(acc[mt][nt], a[mt], &bh[nt >> 1][(nt & 1) * 2]);
            #pragma unroll
            for (int mt = 0; mt < 4; mt++)
                #pragma unroll
                for (int nt = 0; nt < 4; nt++)
                    mma16816(acc[mt][nt], a[mt], &bl[nt >> 1][(nt & 1) * 2]);
            #pragma unroll
            for (int mt = 0; mt < 4; mt++)
                ldm4(a[mt], ab + (uint32_t)(TILE_BYTES + mt * 16 * ROWB));
            #pragma unroll
            for (int mt = 0; mt < 4; mt++)
                #pragma unroll
                for (int nt = 0; nt < 4; nt++)
                    mma16816(acc[mt][nt], a[mt], &bh[nt >> 1][(nt & 1) * 2]);
        }
    }

    // epilogue (predicated, though all grids are exact now)
    const int row0 = mBase + wr * 64 + (lane >> 2);
    const int col0 = nBase + wc * 32 + (lane & 3) * 2;
    #pragma unroll
    for (int mt = 0; mt < 4; mt++) {
        #pragma unroll
        for (int nt = 0; nt < 4; nt++) {
            int cc2 = col0 + nt * 8;
            if (cc2 >= N) continue;
            #pragma unroll
            for (int half = 0; half < 2; half++) {
                int r = row0 + mt * 16 + half * 8;
                if (r >= M) continue;
                size_t pos = (size_t)r * N + cc2;
                float v0 = acc[mt][nt][half * 2 + 0];
                float v1 = acc[mt][nt][half * 2 + 1];
                if (BF16OUT) {
                    __nv_bfloat16 h0 = __float2bfloat16(v0);
                    __nv_bfloat16 h1 = __float2bfloat16(v1);
                    __nv_bfloat162 hp, lp;
                    hp.x = h0; hp.y = h1;
                    lp.x = __float2bfloat16(v0 - __bfloat162float(h0));
                    lp.y = __float2bfloat16(v1 - __bfloat162float(h1));
                    *reinterpret_cast<__nv_bfloat162*>(Ch + pos) = hp;
                    *reinterpret_cast<__nv_bfloat162*>(Cl + pos) = lp;
                } else {
                    *reinterpret_cast<float2*>(Cf + pos) = make_float2(v0, v1);
                }
            }
        }
    }
}

// big GEMMs (fp32 out): z batches A/B/C by aZ/bZ/cZ elements
__global__ __launch_bounds__(256, 2)
void hgemm_main(const __nv_bfloat16* __restrict__ Ah, const __nv_bfloat16* __restrict__ Al,
                const __nv_bfloat16* __restrict__ Bh, const __nv_bfloat16* __restrict__ Bl,
                float* __restrict__ Cf, int M, int N, int K,
                size_t aZ, size_t bZ, size_t cZ) {
    extern __shared__ char smem[];
    const size_t zA = (size_t)blockIdx.z * aZ;
    const size_t zB = (size_t)blockIdx.z * bZ;
    hgemm_core<0>(Ah + zA, Al + zA, Bh + zB, Bl + zB,
                  Cf + (size_t)blockIdx.z * cZ, nullptr, nullptr,
                  M, N, K, blockIdx.y * 128, blockIdx.x * 128, smem);
}

// weight-prep GEMMs (bf16 h/l out), all four in one launch:
//   z<3 : WF_z[N2,D] = NT(TW[N2,D], WT_z[D,D])
//   z=3 : Gt[D,N2]   = NT(Wo[D,D],  TW[N2,D])   (N2 == D == 1024, uniform grid)
__global__ __launch_bounds__(256, 2)
void hgemm_prep() {
    extern __shared__ char smem[];
    const int z = blockIdx.z;
    const __nv_bfloat16 *Ah, *Al, *Bh, *Bl;
    __nv_bfloat16 *Ch, *Cl;
    if (z < 3) {
        Ah = g_TWh; Al = g_TWl;
        Bh = g_WTh + (size_t)z * DDSZ; Bl = g_WTl + (size_t)z * DDSZ;
        Ch = g_WFh + (size_t)z * TWNSZ; Cl = g_WFl + (size_t)z * TWNSZ;
    } else {
        Ah = g_Woh; Al = g_Wol;
        Bh = g_TWh; Bl = g_TWl;
        Ch = g_Gth; Cl = g_Gtl;
    }
    hgemm_core<1>(Ah, Al, Bh, Bl, nullptr, Ch, Cl, N2, D, D,
                  blockIdx.y * 128, blockIdx.x * 128, smem);
}

// ======================= scan kernels =======================
// packed planes: re f at col f (f in [0,513)); im f at col 512+f (f in [1,512));
// im[0] = im[512] = 0 implicitly.
#define pFQ (g_F3)
#define pFKg (g_F3 + FPLANE)
#define pFVg (g_F3 + 2*FPLANE)
#define SCAN_T 544

__global__ __launch_bounds__(SCAN_T) void scan_partial(const int* __restrict__ perms) {
    __shared__ float skr[NF], ski[NF];
    const int b = blockIdx.y, ch = blockIdx.x;
    const int tid = threadIdx.x;
    const int f = tid;
    int   g[CC];
    float ar[CC], ai[CC];
    if (f < NF) {
        #pragma unroll
        for (int c = 0; c < CC; c++) { g[c] = perms[c * NF + f]; ar[c] = 0.f; ai[c] = 0.f; }
    }
    const int t0 = ch * CL;
    for (int t = t0; t < t0 + CL; t++) {
        const size_t row = (size_t)(b * TT + t) * N2;
        for (int i = tid; i < NF; i += SCAN_T) {
            skr[i] = pFKg[row + i];
            ski[i] = (i == 0 || i == IMB) ? 0.f : pFKg[row + IMB + i];
        }
        __syncthreads();
        if (f < NF) {
            float vr = pFVg[row + f];
            float vi = (f == 0 || f == IMB) ? 0.f : pFVg[row + IMB + f];
            #pragma unroll
            for (int c = 0; c < CC; c++) {
                float kr = skr[g[c]], ki = ski[g[c]];
                ar[c] = fmaf(kr, vr, fmaf(-ki, vi, ar[c]));
                ai[c] = fmaf(kr, vi, fmaf( ki, vr, ai[c]));
            }
        }
        __syncthreads();
    }
    if (f < NF) {
        size_t base = (size_t)(b * NCH + ch) * CC * NF + f;
        #pragma unroll
        for (int c = 0; c < CC; c++) {
            g_Sre[base + (size_t)c * NF] = ar[c];
            g_Sim[base + (size_t)c * NF] = ai[c];
        }
    }
}

__global__ void scan_offsets() {
    int idx = blockIdx.x * blockDim.x + threadIdx.x;
    if (idx >= BB * CC * NF) return;
    int f = idx % NF;
    int c = (idx / NF) % CC;
    int b = idx / (NF * CC);
    float rr = 0.f, ri = 0.f;
    for (int ch = 0; ch < NCH; ch++) {
        size_t off = ((size_t)(b * NCH + ch) * CC + c) * NF + f;
        float vr = g_Sre[off], vi = g_Sim[off];
        g_Sre[off] = rr; g_Sim[off] = ri;
        rr += vr; ri += vi;
    }
}

__global__ __launch_bounds__(SCAN_T) void scan_final(const int* __restrict__ perms) {
    __shared__ float skr[NF], ski[NF], sqr[NF], sqi[NF];
    const int b = blockIdx.y, ch = blockIdx.x;
    const int tid = threadIdx.x;
    const int f = tid;
    int   g[CC];
    float ar[CC], ai[CC];
    float s = 0.f;
    if (f < NF) {
        size_t base = (size_t)(b * NCH + ch) * CC * NF + f;
        #pragma unroll
        for (int c = 0; c < CC; c++) {
            g[c]  = perms[c * NF + f];
            ar[c] = g_Sre[base + (size_t)c * NF];
            ai[c] = g_Sim[base + (size_t)c * NF];
        }
        s = ((f == 0 || f == IMB) ? 1.f : 2.f) / ((float)CC * (float)D);
    }
    const int t0 = ch * CL;
    for (int t = t0; t < t0 + CL; t++) {
        const size_t row = (size_t)(b * TT + t) * N2;
        for (int i = tid; i < NF; i += SCAN_T) {
            skr[i] = pFKg[row + i];
            ski[i] = (i == 0 || i == IMB) ? 0.f : pFKg[row + IMB + i];
            sqr[i] = pFQ[row + i];
            sqi[i] = (i == 0 || i == IMB) ? 0.f : pFQ[row + IMB + i];
        }
        __syncthreads();
        if (f < NF) {
            float vr = pFVg[row + f];
            float vi = (f == 0 || f == IMB) ? 0.f : pFVg[row + IMB + f];
            float rr = 0.f, ri = 0.f;
            #pragma unroll
            for (int c = 0; c < CC; c++) {
                float kr = skr[g[c]], ki = ski[g[c]];
                ar[c] = fmaf(kr, vr, fmaf(-ki, vi, ar[c]));
                ai[c] = fmaf(kr, vi, fmaf( ki, vr, ai[c]));
                float qr = sqr[g[c]], qi = sqi[g[c]];
                rr = fmaf(qr, ar[c], fmaf( qi, ai[c], rr));
                ri = fmaf(qr, ai[c], fmaf(-qi, ar[c], ri));
            }
            // packed bf16 hi/lo write: re at f; im at IMB+f (f in [1,512) only)
            float vRe = rr * s;
            __nv_bfloat16 hRe = __float2bfloat16(vRe);
            g_Rh[row + f] = hRe;
            g_Rl[row + f] = __float2bfloat16(vRe - __bfloat162float(hRe));
            if (f >= 1 && f < IMB) {
                float vIm = ri * s;
                __nv_bfloat16 hIm = __float2bfloat16(vIm);
                g_Rh[row + IMB + f] = hIm;
                g_Rl[row + IMB + f] = __float2bfloat16(vIm - __bfloat162float(hIm));
            }
        }
        __syncthreads();
    }
}

// ======================= host launcher =======================
extern "C" void kernel_launch(void* const* d_in, const int* in_sizes, int n_in,
                              void* d_out, int out_size) {
    (void)in_sizes; (void)n_in; (void)out_size;
    const float* x     = (const float*)d_in[0];
    const float* Wq    = (const float*)d_in[1];
    const float* Wk    = (const float*)d_in[2];
    const float* Wv    = (const float*)d_in[3];
    const float* Wo    = (const float*)d_in[4];
    const int*   perms = (const int*)  d_in[5];
    float* out = (float*)d_out;

    cudaFuncSetAttribute(hgemm_main, cudaFuncAttributeMaxDynamicSharedMemorySize, HG_SMEM);
    cudaFuncSetAttribute(hgemm_prep, cudaFuncAttributeMaxDynamicSharedMemorySize, HG_SMEM);

    __nv_bfloat16 *pXh, *pXl, *pWFh, *pWFl, *pGth, *pGtl, *pRh, *pRl;
    float *pF3;
    cudaGetSymbolAddress((void**)&pXh,  g_Xh);  cudaGetSymbolAddress((void**)&pXl,  g_Xl);
    cudaGetSymbolAddress((void**)&pWFh, g_WFh); cudaGetSymbolAddress((void**)&pWFl, g_WFl);
    cudaGetSymbolAddress((void**)&pGth, g_Gth); cudaGetSymbolAddress((void**)&pGtl, g_Gtl);
    cudaGetSymbolAddress((void**)&pRh,  g_Rh);  cudaGetSymbolAddress((void**)&pRl,  g_Rl);
    cudaGetSymbolAddress((void**)&pF3,  g_F3);

    // 0: packed DFT rows (bf16 split written directly)
    build_tw<<<dim3(D / 256, N2), 256>>>();
    // 1: all three weight transposes
    transpose3<<<dim3(32, 32, 3), dim3(32, 8)>>>(Wq, Wk, Wv);
    // 2: bf16 splits (WTcat, Wo, x)
    {
        size_t total = 4*DDSZ + XNSZ;
        split_all<<<(unsigned)((total + 255) / 256), 256>>>(Wo, x);
    }
    // 3: all four weight-prep GEMMs, uniform 1024x1024 tiles
    hgemm_prep<<<dim3(8, 8, 4), 256, HG_SMEM>>>();
    // 4: merged QKV projections+rfft: F3_z = NT(x, WF_z) — exact 8x32 grid
    hgemm_main<<<dim3(8, 32, 3), 256, HG_SMEM>>>(pXh, pXl, pWFh, pWFl,
        pF3, M4, N2, D, 0, TWNSZ, FPLANE);
    // 5-7: causal cumulative bind/unbind (chunked scan over T)
    scan_partial<<<dim3(NCH, BB), SCAN_T>>>(perms);
    scan_offsets<<<(BB * CC * NF + 255) / 256, 256>>>();
    scan_final  <<<dim3(NCH, BB), SCAN_T>>>(perms);
    // 8: irfft + output projection: out = NT(R, Gt), K = 1024
    hgemm_main<<<dim3(8, 32, 1), 256, HG_SMEM>>>(pRh, pRl, pGth, pGtl,
        out, M4, D, N2, 0, 0, 0);
}